// round 11
// baseline (speedup 1.0000x reference)
#include <cuda_runtime.h>

#define Bb 8
#define Tt 800
#define Cc 8
#define Ff 513
#define Aa 320
#define NSYS (Bb*Ff)
#define FB 57        // f per psd block (9*57 = 513 exactly)
#define NFB 9
#define TS 8         // t-chunks
#define TCH 100      // t per chunk
#define PSTRIDE 37   // 36 psd entries + 1 weight-sum, in float2 units

// ---------------- device scratch ----------------
__device__ float2 g_part2[NSYS*2*TS*PSTRIDE];  // psd partials + weight sums
__device__ float2 g_psd_s[NSYS*64];
__device__ float2 g_psd_n[NSYS*64];
__device__ float  g_feat[Bb*Cc*Ff];            // attention features [b][c][f]
__device__ float  g_e[Bb*Cc];
__device__ float2 g_wsc[Bb*Cc*Ff];             // conj(ws), layout (b, c, f)

typedef unsigned long long u64;

__device__ __forceinline__ u64 pk2(float lo, float hi){
    u64 r; asm("mov.b64 %0, {%1, %2};" : "=l"(r) : "f"(lo), "f"(hi)); return r;
}
__device__ __forceinline__ void upk2(float &lo, float &hi, u64 v){
    asm("mov.b64 {%0, %1}, %2;" : "=f"(lo), "=f"(hi) : "l"(v));
}
__device__ __forceinline__ void fma2(u64 &d, u64 a, u64 b){
    asm("fma.rn.f32x2 %0, %1, %2, %0;" : "+l"(d) : "l"(a), "l"(b));
}
__device__ __forceinline__ float2 cmul(float2 a, float2 b){
    return make_float2(a.x*b.x - a.y*b.y, a.x*b.y + a.y*b.x);
}
__device__ __forceinline__ float2 csub(float2 a, float2 b){
    return make_float2(a.x - b.x, a.y - b.y);
}
__device__ __forceinline__ float2 cinv(float2 a){
    float d = 1.f/(a.x*a.x + a.y*a.y);
    return make_float2(a.x*d, -a.y*d);
}

// accumulate one time step into 36 packed accumulators
__device__ __forceinline__ void psd_accum(const float* xr, const float* xi,
                                          float m, u64* acc, float& sumw)
{
    sumw += m;
    u64 av[8], cv[8];
    #pragma unroll
    for (int c = 0; c < 8; c++) {
        av[c] = pk2(xr[c], xi[c]);     // (re, im)
        cv[c] = pk2(xi[c], xr[c]);     // (im, re)
    }
    #pragma unroll
    for (int e = 0; e < 8; e++) {
        float bre = xr[e]*m, bie = xi[e]*m;
        u64 br = pk2(bre,  bre);
        u64 bi = pk2(bie, -bie);
        #pragma unroll
        for (int c = 0; c <= e; c++) {
            int id = (e*(e+1))/2 + c;
            fma2(acc[id], av[c], br);  // re += xr_c*bre, im += xi_c*bre
            fma2(acc[id], cv[c], bi);  // re += xi_c*bie, im -= xr_c*bie
        }
    }
}

// ---------------- K1: fused mask + PSD partials (R5-exact) ---------------
// grid (9, 8, 8), block 128: fi = tid&63 (f lane), msel = tid>>6
__global__ void __launch_bounds__(128) psd_kernel(
    const float* __restrict__ dre, const float* __restrict__ dimg,
    const float* __restrict__ msk_s, const float* __restrict__ msk_n)
{
    __shared__ float s_m[2][FB][TCH+1];   // [mask][f][t]

    const int tid  = threadIdx.x;
    const int fi   = tid & 63;
    const int msel = tid >> 6;
    const int b    = blockIdx.y;
    const int f0   = blockIdx.x * FB;
    const int t0   = blockIdx.z * TCH;
    const int fiC  = fi < FB ? fi : FB-1;
    const int f    = f0 + fiC;

    // ---- mask phase: c-mean of raw masks (scalar, coalesced over t) ----
    for (int i = tid; i < FB*TCH; i += 128) {
        int fl = i / TCH, t = i - fl*TCH;
        const size_t mb = ((size_t)(b*Ff + f0 + fl)*Cc)*Tt + t0 + t;
        const float* ps = msk_s + mb;
        const float* pn = msk_n + mb;
        float ss = 0.f, sn = 0.f;
        #pragma unroll
        for (int c = 0; c < Cc; c++) {
            ss += fmaxf(ps[c*Tt], 1e-6f);
            sn += fmaxf(pn[c*Tt], 1e-6f);
        }
        s_m[0][fl][t] = ss * 0.125f;
        s_m[1][fl][t] = sn * 0.125f;
    }
    __syncthreads();

    const float* msh = &s_m[msel][fiC][0];
    const size_t stepT = (size_t)Cc * Ff;
    const float* pr = dre  + ((size_t)b*Tt + t0)*stepT + f;
    const float* pi = dimg + ((size_t)b*Tt + t0)*stepT + f;

    u64 acc[36];
    #pragma unroll
    for (int i = 0; i < 36; i++) acc[i] = 0ULL;
    float sumw = 0.f;

    // register double-buffer: prefetch t+1 while accumulating t
    float xr0[8], xi0[8], xr1[8], xi1[8];
    #pragma unroll
    for (int c = 0; c < 8; c++) { xr0[c] = pr[c*Ff]; xi0[c] = pi[c*Ff]; }

    #pragma unroll 1
    for (int tt = 0; tt < TCH; tt += 2) {
        const float* prA = pr + (size_t)(tt+1)*stepT;
        const float* piA = pi + (size_t)(tt+1)*stepT;
        #pragma unroll
        for (int c = 0; c < 8; c++) { xr1[c] = prA[c*Ff]; xi1[c] = piA[c*Ff]; }
        psd_accum(xr0, xi0, msh[tt], acc, sumw);
        if (tt + 2 < TCH) {
            const float* prB = pr + (size_t)(tt+2)*stepT;
            const float* piB = pi + (size_t)(tt+2)*stepT;
            #pragma unroll
            for (int c = 0; c < 8; c++) { xr0[c] = prB[c*Ff]; xi0[c] = piB[c*Ff]; }
        }
        psd_accum(xr1, xi1, msh[tt+1], acc, sumw);
    }

    if (fi < FB) {
        float2* dst = g_part2 +
            ((size_t)((b*Ff + f)*2 + msel)*TS + blockIdx.z)*PSTRIDE;
        #pragma unroll
        for (int i = 0; i < 36; i++) {
            float lo, hi; upk2(lo, hi, acc[i]);
            dst[i] = make_float2(lo, hi);
        }
        dst[36] = make_float2(sumw, 0.f);
    }
}

// ---------------- K1b: reduce, normalize, Hermitian expand, features -----
// grid NSYS, block 128: msel = tid>>6, ce = tid&63
__global__ void reduce_kernel()
{
    __shared__ float2 srow[64];
    const int sys = blockIdx.x;
    const int tid = threadIdx.x;
    const int msel = tid >> 6;
    const int ce = tid & 63;
    const int c = ce >> 3, e = ce & 7;
    const int hi = c > e ? c : e;
    const int lo = c > e ? e : c;
    const int id = (hi*(hi+1))/2 + lo;

    const float2* base = g_part2 + ((size_t)(sys*2 + msel)*TS)*PSTRIDE;
    float2 v = make_float2(0.f, 0.f);
    float sw = 0.f;
    #pragma unroll
    for (int ts = 0; ts < TS; ts++) {
        float2 p = base[ts*PSTRIDE + id];
        v.x += p.x; v.y += p.y;
        sw  += base[ts*PSTRIDE + 36].x;
    }
    float inv = 1.f/(sw + 1e-15f);
    v.x *= inv; v.y *= inv;
    if (c > e) v.y = -v.y;
    (msel ? g_psd_n : g_psd_s)[(size_t)sys*64 + ce] = v;

    if (msel == 0) srow[ce] = v;
    __syncthreads();
    if (tid < 8) {       // feature: |mean of off-diagonal row tid| of psd_s
        float sr = 0.f, si = 0.f;
        #pragma unroll
        for (int j = 0; j < 8; j++) { float2 x = srow[tid*8+j]; sr += x.x; si += x.y; }
        float2 d = srow[tid*9]; sr -= d.x; si -= d.y;
        sr *= (1.f/7.f); si *= (1.f/7.f);
        int b = sys / Ff, f = sys - b*Ff;
        g_feat[(size_t)(b*8 + tid)*Ff + f] = sqrtf(sr*sr + si*si);
    }
}

// ---------------- K2: attention MLP -> logits e[b,c] (single kernel) -----
// grid 64 (bc), block 320; mlp_w (657 KB) is L2-resident across blocks
__global__ void attn_kernel(const float* __restrict__ mlp_w,
                            const float* __restrict__ mlp_b,
                            const float* __restrict__ gvw,
                            const float* __restrict__ gvb)
{
    __shared__ float sfeat[Ff];
    __shared__ float red[Aa];
    const int tid = threadIdx.x;
    const int bc  = blockIdx.x;

    for (int f = tid; f < Ff; f += Aa)
        sfeat[f] = g_feat[(size_t)bc*Ff + f];
    __syncthreads();

    float a0 = mlp_b[tid], a1 = 0.f;
    const float* wp = mlp_w + tid;
    #pragma unroll 8
    for (int f = 0; f + 1 < Ff; f += 2) {
        a0 += sfeat[f]   * wp[(size_t)f*Aa];
        a1 += sfeat[f+1] * wp[(size_t)(f+1)*Aa];
    }
    a0 += sfeat[Ff-1] * wp[(size_t)(Ff-1)*Aa];
    red[tid] = tanhf(a0 + a1) * gvw[tid];
    __syncthreads();
    if (tid < 160) red[tid] += red[tid+160]; __syncthreads();
    if (tid <  80) red[tid] += red[tid+ 80]; __syncthreads();
    if (tid <  40) red[tid] += red[tid+ 40]; __syncthreads();
    if (tid <  20) red[tid] += red[tid+ 20]; __syncthreads();
    if (tid <  10) red[tid] += red[tid+ 10]; __syncthreads();
    if (tid == 0) {
        float t = 0.f;
        #pragma unroll
        for (int i = 0; i < 10; i++) t += red[i];
        g_e[bc] = t + gvb[0];
    }
}

// ---------------- K3: MVDR solve, register rows + shfl broadcast ---------
__global__ void __launch_bounds__(256) solve_kernel()
{
    const unsigned FULL = 0xffffffffu;
    const int tid  = threadIdx.x;
    const int warp = tid >> 5, lane = tid & 31;
    const int g = lane >> 3, r = lane & 7;
    const int bl = lane & 24;

    int sys = blockIdx.x*32 + warp*4 + g;
    bool ok = sys < NSYS;
    int sc = ok ? sys : NSYS-1;
    int b = sc / Ff, f = sc - b*Ff;

    float2 A[8], S[8];
    #pragma unroll
    for (int j = 0; j < 8; j++) {
        A[j] = g_psd_n[(size_t)sc*64 + r*8 + j];
        S[j] = g_psd_s[(size_t)sc*64 + r*8 + j];
    }
    A[r].x += 1e-15f;

    float u[8];
    {
        float mx = -1e30f;
        #pragma unroll
        for (int j = 0; j < 8; j++) { u[j] = 2.f*g_e[b*8+j]; mx = fmaxf(mx, u[j]); }
        float s = 0.f;
        #pragma unroll
        for (int j = 0; j < 8; j++) { u[j] = expf(u[j]-mx); s += u[j]; }
        float is = 1.f/s;
        #pragma unroll
        for (int j = 0; j < 8; j++) u[j] *= is;
    }

    #pragma unroll
    for (int k = 0; k < 7; k++) {
        float2 pa[8], ps[8];
        #pragma unroll
        for (int j = 0; j < 8; j++) {
            pa[j].x = __shfl_sync(FULL, A[j].x, bl + k);
            pa[j].y = __shfl_sync(FULL, A[j].y, bl + k);
            ps[j].x = __shfl_sync(FULL, S[j].x, bl + k);
            ps[j].y = __shfl_sync(FULL, S[j].y, bl + k);
        }
        float2 ip = cinv(pa[k]);
        if (r > k) {
            float2 fac = cmul(A[k], ip);
            #pragma unroll
            for (int j = 0; j < 8; j++) {
                A[j] = csub(A[j], cmul(fac, pa[j]));
                S[j] = csub(S[j], cmul(fac, ps[j]));
            }
        }
    }
    #pragma unroll
    for (int k = 7; k >= 0; k--) {
        if (r == k) {
            float2 ip = cinv(A[k]);
            #pragma unroll
            for (int j = 0; j < 8; j++) S[j] = cmul(S[j], ip);
        }
        float2 ps[8];
        #pragma unroll
        for (int j = 0; j < 8; j++) {
            ps[j].x = __shfl_sync(FULL, S[j].x, bl + k);
            ps[j].y = __shfl_sync(FULL, S[j].y, bl + k);
        }
        if (r < k) {
            float2 fac = A[k];
            #pragma unroll
            for (int j = 0; j < 8; j++) S[j] = csub(S[j], cmul(fac, ps[j]));
        }
    }

    float2 tr = make_float2(1e-15f, 0.f);
    #pragma unroll
    for (int j = 0; j < 8; j++) {
        tr.x += __shfl_sync(FULL, S[j].x, bl + j);
        tr.y += __shfl_sync(FULL, S[j].y, bl + j);
    }
    float2 it = cinv(tr);
    float wr = 0.f, wi = 0.f;
    #pragma unroll
    for (int c = 0; c < 8; c++) { wr += S[c].x*u[c]; wi += S[c].y*u[c]; }
    float2 w = cmul(make_float2(wr, wi), it);
    if (ok) g_wsc[(size_t)(b*8+r)*Ff + f] = make_float2(w.x, -w.y);
}

// ---------------- K4: enhanced output ------------------------------------
__global__ void enh_kernel(const float* __restrict__ dre,
                           const float* __restrict__ dimg,
                           float2* __restrict__ out)
{
    __shared__ float2 wsh[8*Ff];
    const int tid = threadIdx.x;
    const int b  = blockIdx.y;
    const int t0 = blockIdx.x * 8;

    for (int i = tid; i < 8*Ff; i += 256)
        wsh[i] = g_wsc[(size_t)b*8*Ff + i];
    __syncthreads();

    for (int tt = 0; tt < 8; tt++) {
        size_t bt = (size_t)b*Tt + t0 + tt;
        const float* pr = dre  + bt*Cc*Ff;
        const float* pi = dimg + bt*Cc*Ff;
        for (int f = tid; f < Ff; f += 256) {
            float er = 0.f, ei = 0.f;
            #pragma unroll
            for (int c = 0; c < 8; c++) {
                float dr = pr[c*Ff + f];
                float di = pi[c*Ff + f];
                float2 w = wsh[c*Ff + f];
                er += w.x*dr - w.y*di;
                ei += w.x*di + w.y*dr;
            }
            out[bt*Ff + f] = make_float2(er, ei);
        }
    }
}

// ---------------- launch --------------------------------------------------
extern "C" void kernel_launch(void* const* d_in, const int* in_sizes, int n_in,
                              void* d_out, int out_size)
{
    const float* dre   = (const float*)d_in[0];
    const float* dimg  = (const float*)d_in[1];
    const float* ms    = (const float*)d_in[2];
    const float* mn    = (const float*)d_in[3];
    const float* mlp_w = (const float*)d_in[4];
    const float* mlp_b = (const float*)d_in[5];
    const float* gvw   = (const float*)d_in[6];
    const float* gvb   = (const float*)d_in[7];
    (void)in_sizes; (void)n_in; (void)out_size;

    psd_kernel<<<dim3(NFB, Bb, TS), 128>>>(dre, dimg, ms, mn);
    reduce_kernel<<<NSYS, 128>>>();
    attn_kernel<<<64, Aa>>>(mlp_w, mlp_b, gvw, gvb);
    solve_kernel<<<(NSYS+31)/32, 256>>>();
    enh_kernel<<<dim3(Tt/8, Bb), 256>>>(dre, dimg, (float2*)d_out);
}

// round 12
// speedup vs baseline: 1.1446x; 1.1446x over previous
#include <cuda_runtime.h>

#define Bb 8
#define Tt 800
#define Cc 8
#define Ff 513
#define Aa 320
#define NSYS (Bb*Ff)
#define FB 57        // f per psd block (9*57 = 513 exactly)
#define NFB 9
#define TS 8         // t-chunks
#define TCH 100      // t per chunk
#define PSTRIDE 37   // 36 psd entries + 1 weight-sum, in float2 units

// ---------------- device scratch ----------------
__device__ float2 g_part2[NSYS*2*TS*PSTRIDE];  // psd partials + weight sums
__device__ float2 g_psd_s[NSYS*64];
__device__ float2 g_psd_n[NSYS*64];
__device__ float  g_e[Bb*Cc];
__device__ float  g_attnpart[64*9*Aa];
__device__ float2 g_wsc[Bb*Cc*Ff];             // conj(ws), layout (b, c, f)

typedef unsigned long long u64;

__device__ __forceinline__ u64 pk2(float lo, float hi){
    u64 r; asm("mov.b64 %0, {%1, %2};" : "=l"(r) : "f"(lo), "f"(hi)); return r;
}
__device__ __forceinline__ void upk2(float &lo, float &hi, u64 v){
    asm("mov.b64 {%0, %1}, %2;" : "=f"(lo), "=f"(hi) : "l"(v));
}
__device__ __forceinline__ void fma2(u64 &d, u64 a, u64 b){
    asm("fma.rn.f32x2 %0, %1, %2, %0;" : "+l"(d) : "l"(a), "l"(b));
}
__device__ __forceinline__ float2 cmul(float2 a, float2 b){
    return make_float2(a.x*b.x - a.y*b.y, a.x*b.y + a.y*b.x);
}
__device__ __forceinline__ float2 csub(float2 a, float2 b){
    return make_float2(a.x - b.x, a.y - b.y);
}
__device__ __forceinline__ float2 cinv(float2 a){
    float d = 1.f/(a.x*a.x + a.y*a.y);
    return make_float2(a.x*d, -a.y*d);
}

// accumulate one time step into 36 packed accumulators
__device__ __forceinline__ void psd_accum(const float* xr, const float* xi,
                                          float m, u64* acc, float& sumw)
{
    sumw += m;
    u64 av[8], cv[8];
    #pragma unroll
    for (int c = 0; c < 8; c++) {
        av[c] = pk2(xr[c], xi[c]);     // (re, im)
        cv[c] = pk2(xi[c], xr[c]);     // (im, re)
    }
    #pragma unroll
    for (int e = 0; e < 8; e++) {
        float bre = xr[e]*m, bie = xi[e]*m;
        u64 br = pk2(bre,  bre);
        u64 bi = pk2(bie, -bie);
        #pragma unroll
        for (int c = 0; c <= e; c++) {
            int id = (e*(e+1))/2 + c;
            fma2(acc[id], av[c], br);  // re += xr_c*bre, im += xi_c*bre
            fma2(acc[id], cv[c], bi);  // re += xi_c*bie, im -= xr_c*bie
        }
    }
}

// ---------------- K1: fused mask + PSD partials --------------------------
// grid (9, 8, 8), block 128: fi = tid&63 (f lane), msel = tid>>6
__global__ void __launch_bounds__(128) psd_kernel(
    const float* __restrict__ dre, const float* __restrict__ dimg,
    const float* __restrict__ msk_s, const float* __restrict__ msk_n)
{
    __shared__ float s_m[2][FB][TCH+1];   // [mask][f][t]

    const int tid  = threadIdx.x;
    const int fi   = tid & 63;
    const int msel = tid >> 6;
    const int b    = blockIdx.y;
    const int f0   = blockIdx.x * FB;
    const int t0   = blockIdx.z * TCH;
    const int fiC  = fi < FB ? fi : FB-1;
    const int f    = f0 + fiC;

    // ---- mask phase: c-mean of raw masks, float4 loads ----
    // alignment: row base = ((b*Ff+f)*8)*800 + t0 + t, all terms = 0 mod 4
    for (int i = tid; i < FB*(TCH/4); i += 128) {
        int fl = i / (TCH/4), tq = i - fl*(TCH/4);
        int t = tq*4;
        const size_t mb = ((size_t)(b*Ff + f0 + fl)*Cc)*Tt + t0 + t;
        const float4* ps = reinterpret_cast<const float4*>(msk_s + mb);
        const float4* pn = reinterpret_cast<const float4*>(msk_n + mb);
        float s0=0.f, s1=0.f, s2=0.f, s3=0.f;
        float n0=0.f, n1=0.f, n2=0.f, n3=0.f;
        #pragma unroll
        for (int c = 0; c < Cc; c++) {
            float4 vs = ps[c*(Tt/4)];
            float4 vn = pn[c*(Tt/4)];
            s0 += fmaxf(vs.x, 1e-6f); s1 += fmaxf(vs.y, 1e-6f);
            s2 += fmaxf(vs.z, 1e-6f); s3 += fmaxf(vs.w, 1e-6f);
            n0 += fmaxf(vn.x, 1e-6f); n1 += fmaxf(vn.y, 1e-6f);
            n2 += fmaxf(vn.z, 1e-6f); n3 += fmaxf(vn.w, 1e-6f);
        }
        s_m[0][fl][t]   = s0 * 0.125f;
        s_m[0][fl][t+1] = s1 * 0.125f;
        s_m[0][fl][t+2] = s2 * 0.125f;
        s_m[0][fl][t+3] = s3 * 0.125f;
        s_m[1][fl][t]   = n0 * 0.125f;
        s_m[1][fl][t+1] = n1 * 0.125f;
        s_m[1][fl][t+2] = n2 * 0.125f;
        s_m[1][fl][t+3] = n3 * 0.125f;
    }
    __syncthreads();

    const float* msh = &s_m[msel][fiC][0];
    const size_t stepT = (size_t)Cc * Ff;
    const float* pr = dre  + ((size_t)b*Tt + t0)*stepT + f;
    const float* pi = dimg + ((size_t)b*Tt + t0)*stepT + f;

    u64 acc[36];
    #pragma unroll
    for (int i = 0; i < 36; i++) acc[i] = 0ULL;
    float sumw = 0.f;

    // register double-buffer: prefetch t+1 while accumulating t
    float xr0[8], xi0[8], xr1[8], xi1[8];
    #pragma unroll
    for (int c = 0; c < 8; c++) { xr0[c] = pr[c*Ff]; xi0[c] = pi[c*Ff]; }

    #pragma unroll 1
    for (int tt = 0; tt < TCH; tt += 2) {
        const float* prA = pr + (size_t)(tt+1)*stepT;
        const float* piA = pi + (size_t)(tt+1)*stepT;
        #pragma unroll
        for (int c = 0; c < 8; c++) { xr1[c] = prA[c*Ff]; xi1[c] = piA[c*Ff]; }
        psd_accum(xr0, xi0, msh[tt], acc, sumw);
        if (tt + 2 < TCH) {
            const float* prB = pr + (size_t)(tt+2)*stepT;
            const float* piB = pi + (size_t)(tt+2)*stepT;
            #pragma unroll
            for (int c = 0; c < 8; c++) { xr0[c] = prB[c*Ff]; xi0[c] = piB[c*Ff]; }
        }
        psd_accum(xr1, xi1, msh[tt+1], acc, sumw);
    }

    if (fi < FB) {
        float2* dst = g_part2 +
            ((size_t)((b*Ff + f)*2 + msel)*TS + blockIdx.z)*PSTRIDE;
        #pragma unroll
        for (int i = 0; i < 36; i++) {
            float lo, hi; upk2(lo, hi, acc[i]);
            dst[i] = make_float2(lo, hi);
        }
        dst[36] = make_float2(sumw, 0.f);
    }
}

// ---------------- K1b: reduce partials, normalize, Hermitian expand ------
// grid NSYS, block 128: msel = tid>>6, ce = tid&63
__global__ void reduce_kernel()
{
    const int sys = blockIdx.x;
    const int tid = threadIdx.x;
    const int msel = tid >> 6;
    const int ce = tid & 63;
    const int c = ce >> 3, e = ce & 7;
    const int hi = c > e ? c : e;
    const int lo = c > e ? e : c;
    const int id = (hi*(hi+1))/2 + lo;

    const float2* base = g_part2 + ((size_t)(sys*2 + msel)*TS)*PSTRIDE;
    float2 v = make_float2(0.f, 0.f);
    float sw = 0.f;
    #pragma unroll
    for (int ts = 0; ts < TS; ts++) {
        float2 p = base[ts*PSTRIDE + id];
        v.x += p.x; v.y += p.y;
        sw  += base[ts*PSTRIDE + 36].x;
    }
    float inv = 1.f/(sw + 1e-15f);
    v.x *= inv; v.y *= inv;
    if (c > e) v.y = -v.y;
    (msel ? g_psd_n : g_psd_s)[(size_t)sys*64 + ce] = v;
}

// ---------------- K2a: attention partial GEMV ----------------------------
__global__ void attn1_kernel(const float* __restrict__ mlp_w)
{
    __shared__ float feat[64];
    const int tid = threadIdx.x;
    const int bc  = blockIdx.y;
    const int b   = bc >> 3;
    const int c   = bc & 7;
    const int fbeg = blockIdx.x * 64;
    const int L = min(64, Ff - fbeg);

    if (tid < L) {
        int f = fbeg + tid;
        const float2* p = g_psd_s + (size_t)(b*Ff + f)*64 + c*8;
        float sr = 0.f, si = 0.f;
        #pragma unroll
        for (int e = 0; e < 8; e++) { float2 v = p[e]; sr += v.x; si += v.y; }
        float2 d = p[c]; sr -= d.x; si -= d.y;
        sr *= (1.f/7.f); si *= (1.f/7.f);
        feat[tid] = sqrtf(sr*sr + si*si);
    }
    __syncthreads();

    float a0 = 0.f, a1 = 0.f;
    const float* wp = mlp_w + (size_t)fbeg*Aa + tid;
    int j = 0;
    #pragma unroll 8
    for (; j + 1 < L; j += 2) {
        a0 += feat[j]   * wp[(size_t)j*Aa];
        a1 += feat[j+1] * wp[(size_t)(j+1)*Aa];
    }
    if (j < L) a0 += feat[j] * wp[(size_t)j*Aa];
    g_attnpart[(bc*9 + blockIdx.x)*Aa + tid] = a0 + a1;
}

__global__ void attn2_kernel(const float* __restrict__ mlp_b,
                             const float* __restrict__ gvw,
                             const float* __restrict__ gvb)
{
    __shared__ float red[Aa];
    const int tid = threadIdx.x;
    const int bc  = blockIdx.x;
    float s = mlp_b[tid];
    #pragma unroll
    for (int ch = 0; ch < 9; ch++) s += g_attnpart[(bc*9 + ch)*Aa + tid];
    red[tid] = tanhf(s) * gvw[tid];
    __syncthreads();
    if (tid < 160) red[tid] += red[tid+160]; __syncthreads();
    if (tid <  80) red[tid] += red[tid+ 80]; __syncthreads();
    if (tid <  40) red[tid] += red[tid+ 40]; __syncthreads();
    if (tid <  20) red[tid] += red[tid+ 20]; __syncthreads();
    if (tid <  10) red[tid] += red[tid+ 10]; __syncthreads();
    if (tid == 0) {
        float t = 0.f;
        #pragma unroll
        for (int i = 0; i < 10; i++) t += red[i];
        g_e[bc] = t + gvb[0];
    }
}

// ---------------- K3: MVDR solve, register rows + shfl broadcast ---------
__global__ void __launch_bounds__(256) solve_kernel()
{
    const unsigned FULL = 0xffffffffu;
    const int tid  = threadIdx.x;
    const int warp = tid >> 5, lane = tid & 31;
    const int g = lane >> 3, r = lane & 7;
    const int bl = lane & 24;

    int sys = blockIdx.x*32 + warp*4 + g;
    bool ok = sys < NSYS;
    int sc = ok ? sys : NSYS-1;
    int b = sc / Ff, f = sc - b*Ff;

    float2 A[8], S[8];
    #pragma unroll
    for (int j = 0; j < 8; j++) {
        A[j] = g_psd_n[(size_t)sc*64 + r*8 + j];
        S[j] = g_psd_s[(size_t)sc*64 + r*8 + j];
    }
    A[r].x += 1e-15f;

    float u[8];
    {
        float mx = -1e30f;
        #pragma unroll
        for (int j = 0; j < 8; j++) { u[j] = 2.f*g_e[b*8+j]; mx = fmaxf(mx, u[j]); }
        float s = 0.f;
        #pragma unroll
        for (int j = 0; j < 8; j++) { u[j] = expf(u[j]-mx); s += u[j]; }
        float is = 1.f/s;
        #pragma unroll
        for (int j = 0; j < 8; j++) u[j] *= is;
    }

    #pragma unroll
    for (int k = 0; k < 7; k++) {
        float2 pa[8], ps[8];
        #pragma unroll
        for (int j = 0; j < 8; j++) {
            pa[j].x = __shfl_sync(FULL, A[j].x, bl + k);
            pa[j].y = __shfl_sync(FULL, A[j].y, bl + k);
            ps[j].x = __shfl_sync(FULL, S[j].x, bl + k);
            ps[j].y = __shfl_sync(FULL, S[j].y, bl + k);
        }
        float2 ip = cinv(pa[k]);
        if (r > k) {
            float2 fac = cmul(A[k], ip);
            #pragma unroll
            for (int j = 0; j < 8; j++) {
                A[j] = csub(A[j], cmul(fac, pa[j]));
                S[j] = csub(S[j], cmul(fac, ps[j]));
            }
        }
    }
    #pragma unroll
    for (int k = 7; k >= 0; k--) {
        if (r == k) {
            float2 ip = cinv(A[k]);
            #pragma unroll
            for (int j = 0; j < 8; j++) S[j] = cmul(S[j], ip);
        }
        float2 ps[8];
        #pragma unroll
        for (int j = 0; j < 8; j++) {
            ps[j].x = __shfl_sync(FULL, S[j].x, bl + k);
            ps[j].y = __shfl_sync(FULL, S[j].y, bl + k);
        }
        if (r < k) {
            float2 fac = A[k];
            #pragma unroll
            for (int j = 0; j < 8; j++) S[j] = csub(S[j], cmul(fac, ps[j]));
        }
    }

    float2 tr = make_float2(1e-15f, 0.f);
    #pragma unroll
    for (int j = 0; j < 8; j++) {
        tr.x += __shfl_sync(FULL, S[j].x, bl + j);
        tr.y += __shfl_sync(FULL, S[j].y, bl + j);
    }
    float2 it = cinv(tr);
    float wr = 0.f, wi = 0.f;
    #pragma unroll
    for (int c = 0; c < 8; c++) { wr += S[c].x*u[c]; wi += S[c].y*u[c]; }
    float2 w = cmul(make_float2(wr, wi), it);
    if (ok) g_wsc[(size_t)(b*8+r)*Ff + f] = make_float2(w.x, -w.y);
}

// ---------------- K4: enhanced output ------------------------------------
__global__ void enh_kernel(const float* __restrict__ dre,
                           const float* __restrict__ dimg,
                           float2* __restrict__ out)
{
    __shared__ float2 wsh[8*Ff];
    const int tid = threadIdx.x;
    const int b  = blockIdx.y;
    const int t0 = blockIdx.x * 8;

    for (int i = tid; i < 8*Ff; i += 256)
        wsh[i] = g_wsc[(size_t)b*8*Ff + i];
    __syncthreads();

    for (int tt = 0; tt < 8; tt++) {
        size_t bt = (size_t)b*Tt + t0 + tt;
        const float* pr = dre  + bt*Cc*Ff;
        const float* pi = dimg + bt*Cc*Ff;
        for (int f = tid; f < Ff; f += 256) {
            float er = 0.f, ei = 0.f;
            #pragma unroll
            for (int c = 0; c < 8; c++) {
                float dr = pr[c*Ff + f];
                float di = pi[c*Ff + f];
                float2 w = wsh[c*Ff + f];
                er += w.x*dr - w.y*di;
                ei += w.x*di + w.y*dr;
            }
            out[bt*Ff + f] = make_float2(er, ei);
        }
    }
}

// ---------------- launch --------------------------------------------------
extern "C" void kernel_launch(void* const* d_in, const int* in_sizes, int n_in,
                              void* d_out, int out_size)
{
    const float* dre   = (const float*)d_in[0];
    const float* dimg  = (const float*)d_in[1];
    const float* ms    = (const float*)d_in[2];
    const float* mn    = (const float*)d_in[3];
    const float* mlp_w = (const float*)d_in[4];
    const float* mlp_b = (const float*)d_in[5];
    const float* gvw   = (const float*)d_in[6];
    const float* gvb   = (const float*)d_in[7];
    (void)in_sizes; (void)n_in; (void)out_size;

    psd_kernel<<<dim3(NFB, Bb, TS), 128>>>(dre, dimg, ms, mn);
    reduce_kernel<<<NSYS, 128>>>();
    attn1_kernel<<<dim3(9, 64), Aa>>>(mlp_w);
    attn2_kernel<<<64, Aa>>>(mlp_b, gvw, gvb);
    solve_kernel<<<(NSYS+31)/32, 256>>>();
    enh_kernel<<<dim3(Tt/8, Bb), 256>>>(dre, dimg, (float2*)d_out);
}

// round 14
// speedup vs baseline: 1.1685x; 1.0208x over previous
#include <cuda_runtime.h>

#define Bb 8
#define Tt 800
#define Cc 8
#define Ff 513
#define Aa 320
#define NSYS (Bb*Ff)
#define FB 57        // f per psd block (9*57 = 513 exactly)
#define NFB 9
#define TS 8         // t-chunks
#define TCH 100      // t per chunk
#define PSTRIDE 37   // 36 psd entries + 1 weight-sum, in float2 units

// ---------------- device scratch ----------------
__device__ float2 g_part2[NSYS*2*TS*PSTRIDE];  // psd partials + weight sums
__device__ float2 g_psd_s[NSYS*64];
__device__ float2 g_psd_n[NSYS*64];
__device__ float  g_e[Bb*Cc];
__device__ float  g_attnpart[64*9*Aa];
__device__ float2 g_wsc[Bb*Cc*Ff];             // conj(ws), layout (b, c, f)

typedef unsigned long long u64;

__device__ __forceinline__ u64 pk2(float lo, float hi){
    u64 r; asm("mov.b64 %0, {%1, %2};" : "=l"(r) : "f"(lo), "f"(hi)); return r;
}
__device__ __forceinline__ void upk2(float &lo, float &hi, u64 v){
    asm("mov.b64 {%0, %1}, %2;" : "=f"(lo), "=f"(hi) : "l"(v));
}
__device__ __forceinline__ void fma2(u64 &d, u64 a, u64 b){
    asm("fma.rn.f32x2 %0, %1, %2, %0;" : "+l"(d) : "l"(a), "l"(b));
}
__device__ __forceinline__ float2 cmul(float2 a, float2 b){
    return make_float2(a.x*b.x - a.y*b.y, a.x*b.y + a.y*b.x);
}
__device__ __forceinline__ float2 csub(float2 a, float2 b){
    return make_float2(a.x - b.x, a.y - b.y);
}
__device__ __forceinline__ float2 cinv(float2 a){
    float d = 1.f/(a.x*a.x + a.y*a.y);
    return make_float2(a.x*d, -a.y*d);
}

// accumulate one time step into 36 packed accumulators
__device__ __forceinline__ void psd_accum(const float* xr, const float* xi,
                                          float m, u64* acc, float& sumw)
{
    sumw += m;
    u64 av[8], cv[8];
    #pragma unroll
    for (int c = 0; c < 8; c++) {
        av[c] = pk2(xr[c], xi[c]);     // (re, im)
        cv[c] = pk2(xi[c], xr[c]);     // (im, re)
    }
    #pragma unroll
    for (int e = 0; e < 8; e++) {
        float bre = xr[e]*m, bie = xi[e]*m;
        u64 br = pk2(bre,  bre);
        u64 bi = pk2(bie, -bie);
        #pragma unroll
        for (int c = 0; c <= e; c++) {
            int id = (e*(e+1))/2 + c;
            fma2(acc[id], av[c], br);  // re += xr_c*bre, im += xi_c*bre
            fma2(acc[id], cv[c], bi);  // re += xi_c*bie, im -= xr_c*bie
        }
    }
}

// ---------------- K1: fused mask + PSD partials --------------------------
// grid (9, 8, 8), block 128: fi = tid&63 (f lane), msel = tid>>6
__global__ void __launch_bounds__(128) psd_kernel(
    const float* __restrict__ dre, const float* __restrict__ dimg,
    const float* __restrict__ msk_s, const float* __restrict__ msk_n)
{
    __shared__ float s_m[2][FB][TCH+1];   // [mask][f][t]

    const int tid  = threadIdx.x;
    const int fi   = tid & 63;
    const int msel = tid >> 6;
    const int b    = blockIdx.y;
    const int f0   = blockIdx.x * FB;
    const int t0   = blockIdx.z * TCH;
    const int fiC  = fi < FB ? fi : FB-1;
    const int f    = f0 + fiC;

    // ---- mask phase: c-mean of raw masks, float4 loads ----
    // alignment: row base = ((b*Ff+f)*8)*800 + t0 + t, all terms = 0 mod 4
    for (int i = tid; i < FB*(TCH/4); i += 128) {
        int fl = i / (TCH/4), tq = i - fl*(TCH/4);
        int t = tq*4;
        const size_t mb = ((size_t)(b*Ff + f0 + fl)*Cc)*Tt + t0 + t;
        const float4* ps = reinterpret_cast<const float4*>(msk_s + mb);
        const float4* pn = reinterpret_cast<const float4*>(msk_n + mb);
        float s0=0.f, s1=0.f, s2=0.f, s3=0.f;
        float n0=0.f, n1=0.f, n2=0.f, n3=0.f;
        #pragma unroll
        for (int c = 0; c < Cc; c++) {
            float4 vs = ps[c*(Tt/4)];
            float4 vn = pn[c*(Tt/4)];
            s0 += fmaxf(vs.x, 1e-6f); s1 += fmaxf(vs.y, 1e-6f);
            s2 += fmaxf(vs.z, 1e-6f); s3 += fmaxf(vs.w, 1e-6f);
            n0 += fmaxf(vn.x, 1e-6f); n1 += fmaxf(vn.y, 1e-6f);
            n2 += fmaxf(vn.z, 1e-6f); n3 += fmaxf(vn.w, 1e-6f);
        }
        s_m[0][fl][t]   = s0 * 0.125f;
        s_m[0][fl][t+1] = s1 * 0.125f;
        s_m[0][fl][t+2] = s2 * 0.125f;
        s_m[0][fl][t+3] = s3 * 0.125f;
        s_m[1][fl][t]   = n0 * 0.125f;
        s_m[1][fl][t+1] = n1 * 0.125f;
        s_m[1][fl][t+2] = n2 * 0.125f;
        s_m[1][fl][t+3] = n3 * 0.125f;
    }
    __syncthreads();

    const float* msh = &s_m[msel][fiC][0];
    const size_t stepT = (size_t)Cc * Ff;
    const float* pr = dre  + ((size_t)b*Tt + t0)*stepT + f;
    const float* pi = dimg + ((size_t)b*Tt + t0)*stepT + f;

    u64 acc[36];
    #pragma unroll
    for (int i = 0; i < 36; i++) acc[i] = 0ULL;
    float sumw = 0.f;

    // register double-buffer: prefetch t+1 while accumulating t
    float xr0[8], xi0[8], xr1[8], xi1[8];
    #pragma unroll
    for (int c = 0; c < 8; c++) { xr0[c] = pr[c*Ff]; xi0[c] = pi[c*Ff]; }

    #pragma unroll 1
    for (int tt = 0; tt < TCH; tt += 2) {
        const float* prA = pr + (size_t)(tt+1)*stepT;
        const float* piA = pi + (size_t)(tt+1)*stepT;
        #pragma unroll
        for (int c = 0; c < 8; c++) { xr1[c] = prA[c*Ff]; xi1[c] = piA[c*Ff]; }
        psd_accum(xr0, xi0, msh[tt], acc, sumw);
        if (tt + 2 < TCH) {
            const float* prB = pr + (size_t)(tt+2)*stepT;
            const float* piB = pi + (size_t)(tt+2)*stepT;
            #pragma unroll
            for (int c = 0; c < 8; c++) { xr0[c] = prB[c*Ff]; xi0[c] = piB[c*Ff]; }
        }
        psd_accum(xr1, xi1, msh[tt+1], acc, sumw);
    }

    if (fi < FB) {
        float2* dst = g_part2 +
            ((size_t)((b*Ff + f)*2 + msel)*TS + blockIdx.z)*PSTRIDE;
        #pragma unroll
        for (int i = 0; i < 36; i++) {
            float lo, hi; upk2(lo, hi, acc[i]);
            dst[i] = make_float2(lo, hi);
        }
        dst[36] = make_float2(sumw, 0.f);
    }
}

// ---------------- K1b: reduce partials, normalize, Hermitian expand ------
// grid NSYS, block 128: msel = tid>>6, ce = tid&63
__global__ void reduce_kernel()
{
    const int sys = blockIdx.x;
    const int tid = threadIdx.x;
    const int msel = tid >> 6;
    const int ce = tid & 63;
    const int c = ce >> 3, e = ce & 7;
    const int hi = c > e ? c : e;
    const int lo = c > e ? e : c;
    const int id = (hi*(hi+1))/2 + lo;

    const float2* base = g_part2 + ((size_t)(sys*2 + msel)*TS)*PSTRIDE;
    float2 v = make_float2(0.f, 0.f);
    float sw = 0.f;
    #pragma unroll
    for (int ts = 0; ts < TS; ts++) {
        float2 p = base[ts*PSTRIDE + id];
        v.x += p.x; v.y += p.y;
        sw  += base[ts*PSTRIDE + 36].x;
    }
    float inv = 1.f/(sw + 1e-15f);
    v.x *= inv; v.y *= inv;
    if (c > e) v.y = -v.y;
    (msel ? g_psd_n : g_psd_s)[(size_t)sys*64 + ce] = v;
}

// ---------------- K2a: attention partial GEMV (4 accumulators) -----------
__global__ void attn1_kernel(const float* __restrict__ mlp_w)
{
    __shared__ float feat[64];
    const int tid = threadIdx.x;
    const int bc  = blockIdx.y;
    const int b   = bc >> 3;
    const int c   = bc & 7;
    const int fbeg = blockIdx.x * 64;
    const int L = min(64, Ff - fbeg);

    if (tid < L) {
        int f = fbeg + tid;
        const float2* p = g_psd_s + (size_t)(b*Ff + f)*64 + c*8;
        float sr = 0.f, si = 0.f;
        #pragma unroll
        for (int e = 0; e < 8; e++) { float2 v = p[e]; sr += v.x; si += v.y; }
        float2 d = p[c]; sr -= d.x; si -= d.y;
        sr *= (1.f/7.f); si *= (1.f/7.f);
        feat[tid] = sqrtf(sr*sr + si*si);
    }
    __syncthreads();

    float a0 = 0.f, a1 = 0.f, a2 = 0.f, a3 = 0.f;
    const float* wp = mlp_w + (size_t)fbeg*Aa + tid;
    int j = 0;
    #pragma unroll 4
    for (; j + 3 < L; j += 4) {
        a0 += feat[j]   * wp[(size_t)j*Aa];
        a1 += feat[j+1] * wp[(size_t)(j+1)*Aa];
        a2 += feat[j+2] * wp[(size_t)(j+2)*Aa];
        a3 += feat[j+3] * wp[(size_t)(j+3)*Aa];
    }
    for (; j < L; j++) a0 += feat[j] * wp[(size_t)j*Aa];
    g_attnpart[(bc*9 + blockIdx.x)*Aa + tid] = (a0 + a1) + (a2 + a3);
}

__global__ void attn2_kernel(const float* __restrict__ mlp_b,
                             const float* __restrict__ gvw,
                             const float* __restrict__ gvb)
{
    __shared__ float red[Aa];
    const int tid = threadIdx.x;
    const int bc  = blockIdx.x;
    float s = mlp_b[tid];
    #pragma unroll
    for (int ch = 0; ch < 9; ch++) s += g_attnpart[(bc*9 + ch)*Aa + tid];
    red[tid] = tanhf(s) * gvw[tid];
    __syncthreads();
    if (tid < 160) red[tid] += red[tid+160]; __syncthreads();
    if (tid <  80) red[tid] += red[tid+ 80]; __syncthreads();
    if (tid <  40) red[tid] += red[tid+ 40]; __syncthreads();
    if (tid <  20) red[tid] += red[tid+ 20]; __syncthreads();
    if (tid <  10) red[tid] += red[tid+ 10]; __syncthreads();
    if (tid == 0) {
        float t = 0.f;
        #pragma unroll
        for (int i = 0; i < 10; i++) t += red[i];
        g_e[bc] = t + gvb[0];
    }
}

// ---------------- K3: MVDR solve, register rows + shfl broadcast ---------
// Dead-work trimmed: forward step k only shuffles pa[j] (j>=k) and only
// updates A[j] (j>k) — sub-diagonal A entries are never read afterward.
__global__ void __launch_bounds__(256) solve_kernel()
{
    const unsigned FULL = 0xffffffffu;
    const int tid  = threadIdx.x;
    const int warp = tid >> 5, lane = tid & 31;
    const int g = lane >> 3, r = lane & 7;
    const int bl = lane & 24;

    int sys = blockIdx.x*32 + warp*4 + g;
    bool ok = sys < NSYS;
    int sc = ok ? sys : NSYS-1;
    int b = sc / Ff, f = sc - b*Ff;

    float2 A[8], S[8];
    #pragma unroll
    for (int j = 0; j < 8; j++) {
        A[j] = g_psd_n[(size_t)sc*64 + r*8 + j];
        S[j] = g_psd_s[(size_t)sc*64 + r*8 + j];
    }
    A[r].x += 1e-15f;

    float u[8];
    {
        float mx = -1e30f;
        #pragma unroll
        for (int j = 0; j < 8; j++) { u[j] = 2.f*g_e[b*8+j]; mx = fmaxf(mx, u[j]); }
        float s = 0.f;
        #pragma unroll
        for (int j = 0; j < 8; j++) { u[j] = expf(u[j]-mx); s += u[j]; }
        float is = 1.f/s;
        #pragma unroll
        for (int j = 0; j < 8; j++) u[j] *= is;
    }

    #pragma unroll
    for (int k = 0; k < 7; k++) {
        float2 pa[8], ps[8];
        #pragma unroll
        for (int j = k; j < 8; j++) {       // only j>=k needed for A math
            pa[j].x = __shfl_sync(FULL, A[j].x, bl + k);
            pa[j].y = __shfl_sync(FULL, A[j].y, bl + k);
        }
        #pragma unroll
        for (int j = 0; j < 8; j++) {
            ps[j].x = __shfl_sync(FULL, S[j].x, bl + k);
            ps[j].y = __shfl_sync(FULL, S[j].y, bl + k);
        }
        float2 ip = cinv(pa[k]);
        if (r > k) {
            float2 fac = cmul(A[k], ip);
            #pragma unroll
            for (int j = k+1; j < 8; j++)   // col k becomes 0, never read
                A[j] = csub(A[j], cmul(fac, pa[j]));
            #pragma unroll
            for (int j = 0; j < 8; j++)
                S[j] = csub(S[j], cmul(fac, ps[j]));
        }
    }
    #pragma unroll
    for (int k = 7; k >= 0; k--) {
        if (r == k) {
            float2 ip = cinv(A[k]);
            #pragma unroll
            for (int j = 0; j < 8; j++) S[j] = cmul(S[j], ip);
        }
        float2 ps[8];
        #pragma unroll
        for (int j = 0; j < 8; j++) {
            ps[j].x = __shfl_sync(FULL, S[j].x, bl + k);
            ps[j].y = __shfl_sync(FULL, S[j].y, bl + k);
        }
        if (r < k) {
            float2 fac = A[k];
            #pragma unroll
            for (int j = 0; j < 8; j++) S[j] = csub(S[j], cmul(fac, ps[j]));
        }
    }

    float2 tr = make_float2(1e-15f, 0.f);
    #pragma unroll
    for (int j = 0; j < 8; j++) {
        tr.x += __shfl_sync(FULL, S[j].x, bl + j);
        tr.y += __shfl_sync(FULL, S[j].y, bl + j);
    }
    float2 it = cinv(tr);
    float wr = 0.f, wi = 0.f;
    #pragma unroll
    for (int c = 0; c < 8; c++) { wr += S[c].x*u[c]; wi += S[c].y*u[c]; }
    float2 w = cmul(make_float2(wr, wi), it);
    if (ok) g_wsc[(size_t)(b*8+r)*Ff + f] = make_float2(w.x, -w.y);
}

// ---------------- K4: enhanced output ------------------------------------
__global__ void enh_kernel(const float* __restrict__ dre,
                           const float* __restrict__ dimg,
                           float2* __restrict__ out)
{
    __shared__ float2 wsh[8*Ff];
    const int tid = threadIdx.x;
    const int b  = blockIdx.y;
    const int t0 = blockIdx.x * 8;

    for (int i = tid; i < 8*Ff; i += 256)
        wsh[i] = g_wsc[(size_t)b*8*Ff + i];
    __syncthreads();

    for (int tt = 0; tt < 8; tt++) {
        size_t bt = (size_t)b*Tt + t0 + tt;
        const float* pr = dre  + bt*Cc*Ff;
        const float* pi = dimg + bt*Cc*Ff;
        for (int f = tid; f < Ff; f += 256) {
            float er = 0.f, ei = 0.f;
            #pragma unroll
            for (int c = 0; c < 8; c++) {
                float dr = pr[c*Ff + f];
                float di = pi[c*Ff + f];
                float2 w = wsh[c*Ff + f];
                er += w.x*dr - w.y*di;
                ei += w.x*di + w.y*dr;
            }
            out[bt*Ff + f] = make_float2(er, ei);
        }
    }
}

// ---------------- launch --------------------------------------------------
extern "C" void kernel_launch(void* const* d_in, const int* in_sizes, int n_in,
                              void* d_out, int out_size)
{
    const float* dre   = (const float*)d_in[0];
    const float* dimg  = (const float*)d_in[1];
    const float* ms    = (const float*)d_in[2];
    const float* mn    = (const float*)d_in[3];
    const float* mlp_w = (const float*)d_in[4];
    const float* mlp_b = (const float*)d_in[5];
    const float* gvw   = (const float*)d_in[6];
    const float* gvb   = (const float*)d_in[7];
    (void)in_sizes; (void)n_in; (void)out_size;

    psd_kernel<<<dim3(NFB, Bb, TS), 128>>>(dre, dimg, ms, mn);
    reduce_kernel<<<NSYS, 128>>>();
    attn1_kernel<<<dim3(9, 64), Aa>>>(mlp_w);
    attn2_kernel<<<64, Aa>>>(mlp_b, gvw, gvb);
    solve_kernel<<<(NSYS+31)/32, 256>>>();
    enh_kernel<<<dim3(Tt/8, Bb), 256>>>(dre, dimg, (float2*)d_out);
}